// round 16
// baseline (speedup 1.0000x reference)
#include <cuda_runtime.h>
#include <cuda_bf16.h>
#include <cuda_fp16.h>
#include <math.h>
#include <stdint.h>

// Fixed problem shape
#define BB 2
#define SEQ 2048
#define DIM 1024
#define NH 16
#define HD 64
#define MTOT (BB * SEQ)            // 4096
#define K2 (2 * DIM)               // 2048 (2-term fp16 split layout)
#define NSTG2 32                   // K2 / 64
#define NBH (BB * NH)              // 32
#define LOG2E 1.44269504f

// ---------------- scratch ----------------------------------------------------
__device__ float g_gate[(size_t)MTOT * DIM];           // sigmoid gate fp32
__device__ __half g_E[(size_t)NBH * SEQ * SEQ];        // unnormalized exp, fp16
__device__ float g_rinv[(size_t)NBH * SEQ];            // 1/rowsum
__device__ __half g_a2[(size_t)MTOT * K2];             // [Ah|Al] fp16 (x, then att)
__device__ __half g_w2[5ull * DIM * K2];               // [Wh|Wh] fp16 N-major
__device__ __half g_qkh[3ull * 2 * NBH * SEQ * HD];    // q,k,v per-head fp16 (hi slots)
__device__ __half g_maskh[(size_t)BB * SEQ * SEQ];     // (mask*log2e) | pad->-60000

// ======================= helpers ===========================================
__device__ __forceinline__ uint32_t smem_u32(const void* p) {
    uint32_t a;
    asm("{ .reg .u64 t; cvta.to.shared.u64 t, %1; cvt.u32.u64 %0, t; }"
        : "=r"(a) : "l"(p));
    return a;
}
__device__ __forceinline__ uint32_t swz128(uint32_t o) { return o ^ ((o >> 3) & 0x70); }

__device__ __forceinline__ void cp_async16(uint32_t dst, const void* src) {
    asm volatile("cp.async.cg.shared.global [%0], [%1], 16;" :: "r"(dst), "l"(src));
}
#define CP_COMMIT() asm volatile("cp.async.commit_group;" ::: "memory")
#define CP_WAIT(n)  asm volatile("cp.async.wait_group %0;" :: "n"(n) : "memory")

__device__ __forceinline__ void ldmx4(uint32_t* r, uint32_t addr) {
    asm volatile("ldmatrix.sync.aligned.m8n8.x4.shared.b16 {%0,%1,%2,%3}, [%4];"
                 : "=r"(r[0]), "=r"(r[1]), "=r"(r[2]), "=r"(r[3]) : "r"(addr));
}
__device__ __forceinline__ void ldmx4t(uint32_t* r, uint32_t addr) {
    asm volatile("ldmatrix.sync.aligned.m8n8.x4.trans.shared.b16 {%0,%1,%2,%3}, [%4];"
                 : "=r"(r[0]), "=r"(r[1]), "=r"(r[2]), "=r"(r[3]) : "r"(addr));
}
__device__ __forceinline__ void mma_hf(float* c, const uint32_t* a, const uint32_t* b) {
    asm volatile(
        "mma.sync.aligned.m16n8k16.row.col.f32.f16.f16.f32 "
        "{%0,%1,%2,%3}, {%4,%5,%6,%7}, {%8,%9}, {%0,%1,%2,%3};"
        : "+f"(c[0]), "+f"(c[1]), "+f"(c[2]), "+f"(c[3])
        : "r"(a[0]), "r"(a[1]), "r"(a[2]), "r"(a[3]), "r"(b[0]), "r"(b[1]));
}
__device__ __forceinline__ uint32_t h2ex2(uint32_t s) {
    uint32_t r;
    asm("ex2.approx.f16x2 %0, %1;" : "=r"(r) : "r"(s));
    return r;
}

// ======================= conversions =======================================
__global__ __launch_bounds__(256) void split2_f32(const float* __restrict__ x,
                                                  __half* __restrict__ A2) {
    size_t i = ((size_t)blockIdx.x * 256 + threadIdx.x) * 4;
    size_t m = i / DIM, k = i % DIM;
    float4 v = *reinterpret_cast<const float4*>(x + i);
    __half h0 = __float2half_rn(v.x), h1 = __float2half_rn(v.y);
    __half h2 = __float2half_rn(v.z), h3 = __float2half_rn(v.w);
    __half2 hA(h0, h1), hB(h2, h3);
    __half2 lA(__float2half_rn(v.x - __half2float(h0)),
               __float2half_rn(v.y - __half2float(h1)));
    __half2 lB(__float2half_rn(v.z - __half2float(h2)),
               __float2half_rn(v.w - __half2float(h3)));
    __half* row = A2 + m * K2;
    *reinterpret_cast<__half2*>(row + k) = hA;
    *reinterpret_cast<__half2*>(row + k + 2) = hB;
    *reinterpret_cast<__half2*>(row + DIM + k) = lA;
    *reinterpret_cast<__half2*>(row + DIM + k + 2) = lB;
}

__global__ __launch_bounds__(1024) void transpose_split2_all(
    const float* __restrict__ W0, const float* __restrict__ W1,
    const float* __restrict__ W2p, const float* __restrict__ W3p,
    const float* __restrict__ W4, __half* __restrict__ out)
{
    __shared__ float t[32][33];
    int z = blockIdx.z;
    const float* W = (z == 0) ? W0 : (z == 1) ? W1 : (z == 2) ? W2p : (z == 3) ? W3p : W4;
    int tx = threadIdx.x, ty = threadIdx.y;
    int k0 = blockIdx.y * 32, n0 = blockIdx.x * 32;
    t[ty][tx] = W[(size_t)(k0 + ty) * DIM + n0 + tx];
    __syncthreads();
    float v = t[tx][ty];
    __half h = __float2half_rn(v);
    __half* row = out + (size_t)z * DIM * K2 + (size_t)(n0 + ty) * K2;
    row[k0 + tx] = h;
    row[DIM + k0 + tx] = h;
}

// mask -> fp16 * log2e, padded keys -> -60000 (ex2 underflows to 0)
__global__ __launch_bounds__(256) void mask_pad_to_half(
    const float* __restrict__ m, const unsigned char* __restrict__ pad,
    __half* __restrict__ mh)
{
    int b = blockIdx.y;
    size_t i = ((size_t)blockIdx.x * 256 + threadIdx.x) * 4;
    int kc = (int)(i & (SEQ - 1));
    float4 v = *reinterpret_cast<const float4*>(m + i);
    uchar4 pd = *reinterpret_cast<const uchar4*>(pad + b * SEQ + kc);
    const float NEG = -60000.f;
    float a0 = pd.x ? NEG : v.x * LOG2E;
    float a1 = pd.y ? NEG : v.y * LOG2E;
    float a2v = pd.z ? NEG : v.z * LOG2E;
    float a3 = pd.w ? NEG : v.w * LOG2E;
    __half2 A = __floats2half2_rn(a0, a1);
    __half2 Bv = __floats2half2_rn(a2v, a3);
    __half* dst = mh + (size_t)b * SEQ * SEQ + i;
    *reinterpret_cast<__half2*>(dst) = A;
    *reinterpret_cast<__half2*>(dst + 2) = Bv;
}

// ======================= HMMA fp16 dense GEMM (3-stage) ====================
#define GEMM_SMEM (96 * 1024)
__global__ __launch_bounds__(256, 2) void gemm_hmma(
    const __half* __restrict__ A2, const __half* __restrict__ W2base,
    const float* b0, const float* b1, const float* b2, const float* b3,
    float* __restrict__ gateOut, __half* __restrict__ qkhOut,
    float* __restrict__ fOut, int mode)
{
    extern __shared__ char smem[];
    const uint32_t sb = smem_u32(smem);
    const int tid = threadIdx.x;
    const int wid = tid >> 5, lane = tid & 31;
    const int wm = wid & 3, wn = wid >> 2;
    const int z = blockIdx.z;
    const int m0 = blockIdx.y * 128, n0 = blockIdx.x * 128;

    const int nstg = (mode == 1) ? NSTG2 : (NSTG2 / 2);

    const __half* W2 = W2base + (size_t)z * DIM * K2;
    const float* bias = (z == 0) ? b0 : (z == 1) ? b1 : (z == 2) ? b2 : b3;

    const char* gA = (const char*)(A2 + (size_t)m0 * K2);
    const char* gB = (const char*)(W2 + (size_t)n0 * K2);

    auto load_stage = [&](int s) {
        const uint32_t base = sb + (s % 3) * 32768;
        const int kb = s * 128;
#pragma unroll
        for (int i = 0; i < 4; i++) {
            int c = tid + 256 * i;
            int row = c >> 3, cb = (c & 7) * 16;
            uint32_t d = swz128(row * 128 + cb);
            size_t src = (size_t)row * (K2 * 2) + kb + cb;
            cp_async16(base + d, gA + src);
            cp_async16(base + 16384 + d, gB + src);
        }
        CP_COMMIT();
    };

    float acc[2][8][4];
#pragma unroll
    for (int mi = 0; mi < 2; mi++)
#pragma unroll
        for (int ni = 0; ni < 8; ni++)
#pragma unroll
            for (int j = 0; j < 4; j++) acc[mi][ni][j] = 0.f;

    load_stage(0);
    load_stage(1);
    load_stage(2);

    for (int s = 0; s < nstg; s++) {
        if (s >= nstg - 1)      { CP_WAIT(0); }
        else if (s == nstg - 2) { CP_WAIT(1); }
        else                    { CP_WAIT(2); }
        __syncthreads();
        const uint32_t abase = sb + (s % 3) * 32768;
        const uint32_t bbase = abase + 16384;
#pragma unroll
        for (int ki = 0; ki < 4; ki++) {
            uint32_t a[2][4];
#pragma unroll
            for (int mi = 0; mi < 2; mi++) {
                int row = wm * 32 + mi * 16 + (lane & 15);
                int kb = ki * 32 + ((lane >> 4) << 4);
                ldmx4(a[mi], abase + swz128(row * 128 + kb));
            }
#pragma unroll
            for (int pi = 0; pi < 4; pi++) {
                int nrow = wn * 64 + pi * 16 + ((lane >> 4) << 3) + (lane & 7);
                int kb = ki * 32 + ((lane >> 3) & 1) * 16;
                uint32_t b[4];
                ldmx4(b, bbase + swz128(nrow * 128 + kb));
#pragma unroll
                for (int mi = 0; mi < 2; mi++) {
                    mma_hf(acc[mi][2 * pi], a[mi], b);
                    mma_hf(acc[mi][2 * pi + 1], a[mi], b + 2);
                }
            }
        }
        __syncthreads();
        if (s + 3 < nstg) load_stage(s + 3);
    }

    const int rbase = m0 + wm * 32;
    const int cbase = n0 + wn * 64;
#pragma unroll
    for (int mi = 0; mi < 2; mi++) {
#pragma unroll
        for (int ni = 0; ni < 8; ni++) {
            int row = rbase + mi * 16 + (lane >> 2);
            int col = cbase + ni * 8 + (lane & 3) * 2;
            float bx = bias[col], by = bias[col + 1];
            float vx0 = acc[mi][ni][0] + bx, vy0 = acc[mi][ni][1] + by;
            float vx1 = acc[mi][ni][2] + bx, vy1 = acc[mi][ni][3] + by;
            if (mode == 1) {
                *reinterpret_cast<float2*>(&fOut[(size_t)row * DIM + col]) =
                    make_float2(vx0, vy0);
                *reinterpret_cast<float2*>(&fOut[(size_t)(row + 8) * DIM + col]) =
                    make_float2(vx1, vy1);
            } else if (z == 3) {
                float2 g0 = {1.f / (1.f + expf(-vx0)), 1.f / (1.f + expf(-vy0))};
                float2 g1 = {1.f / (1.f + expf(-vx1)), 1.f / (1.f + expf(-vy1))};
                *reinterpret_cast<float2*>(&gateOut[(size_t)row * DIM + col]) = g0;
                *reinterpret_cast<float2*>(&gateOut[(size_t)(row + 8) * DIM + col]) = g1;
            } else {
                if (z == 0) {
                    const float sc = 0.125f * LOG2E;
                    vx0 *= sc; vy0 *= sc; vx1 *= sc; vy1 *= sc;
                }
                int h = col >> 6, d = col & 63;
#pragma unroll
                for (int rr = 0; rr < 2; rr++) {
                    int rw = row + rr * 8;
                    float vx = rr ? vx1 : vx0, vy = rr ? vy1 : vy0;
                    int bh = (rw >> 11) * NH + h, s = rw & 2047;
                    __half2 hi2(__float2half_rn(vx), __float2half_rn(vy));
                    size_t bi = ((((size_t)z * 2 + 0) * NBH + bh) * SEQ + s) * HD + d;
                    *reinterpret_cast<__half2*>(qkhOut + bi) = hi2;
                }
            }
        }
    }
}

// ======================= fused flash attention v10 =========================
// QK 1-term fp16 log2 domain, E = ex2.approx.f16x2(S + foldedMask), PV 1-term.
// Rowsum via E @ ones. ONE barrier per TWO k-tiles (4 KV stages):
//   CP_WAIT(0) -> barrier -> issue loads for tiles 2p+2,2p+3 (freed stages)
//   -> process tile 2p -> process tile 2p+1.
// smem: QH 0 (16K) | stages 16K+s*16K (4x16K) | staging 80K (16K). 96K, 2 CTAs/SM.
#define FL_SMEM (96 * 1024)
#define STG_OFF (80 * 1024)
#define NKB 32
__global__ __launch_bounds__(256, 2) void flash_attn(
    const __half* __restrict__ qkh, const __half* __restrict__ maskh,
    const float* __restrict__ gate,
    __half* __restrict__ E, float* __restrict__ rinv,
    __half* __restrict__ att2)
{
    extern __shared__ char smem[];
    const uint32_t sb = smem_u32(smem);
    const int tid = threadIdx.x;
    const int w = tid >> 5, lane = tid & 31;
    const int bhz = blockIdx.z, qb = blockIdx.y;
    const int bb = bhz >> 4, hh = bhz & 15;

    const __half* Qh = qkh + ((size_t)(0 * 2 + 0) * NBH + bhz) * SEQ * HD;
    const __half* Kh = qkh + ((size_t)(1 * 2 + 0) * NBH + bhz) * SEQ * HD;
    const __half* Vh = qkh + ((size_t)(2 * 2 + 0) * NBH + bhz) * SEQ * HD;
    const __half* Mb = maskh + (size_t)bb * SEQ * SEQ;

#pragma unroll
    for (int i = 0; i < 4; i++) {
        int c = tid + 256 * i;
        int row = c >> 3, cb = (c & 7) * 16;
        uint32_t d = swz128(row * 128 + cb);
        size_t src = (size_t)(qb * 128 + row) * (HD * 2) + cb;
        cp_async16(sb + d, (const char*)Qh + src);
    }
    auto load_kv = [&](int kb) {
        const uint32_t base = sb + 16384 + (kb & 3) * 16384;
#pragma unroll
        for (int i = 0; i < 2; i++) {
            int c = tid + 256 * i;
            int row = c >> 3, cb = (c & 7) * 16;
            uint32_t d = swz128(row * 128 + cb);
            size_t src = (size_t)(kb * 64 + row) * (HD * 2) + cb;
            cp_async16(base + d, (const char*)Kh + src);
            cp_async16(base + 8192 + d, (const char*)Vh + src);
        }
        CP_COMMIT();
    };
    load_kv(0);     // group 0 also covers Q loads
    load_kv(1);
    load_kv(2);
    load_kv(3);

    float O[8][4];
#pragma unroll
    for (int ni = 0; ni < 8; ni++)
#pragma unroll
        for (int j = 0; j < 4; j++) O[ni][j] = 0.f;

    float rsA[4] = {0.f, 0.f, 0.f, 0.f};
    const uint32_t ONE2 = 0x3C003C00u;
    const uint32_t b_ones[2] = {ONE2, ONE2};

    const int r0l = w * 16 + (lane >> 2);
    const int q_r0 = qb * 128 + r0l;
    const int q_r1 = q_r0 + 8;
    __half* Eb = E + (size_t)bhz * SEQ * SEQ;

    // warp-local coalesced E store (each warp owns staging rows [16w,16w+16))
    auto store_E = [&](int t) {
#pragma unroll
        for (int i = 0; i < 4; i++) {
            int idx = i * 32 + lane;
            int row = w * 16 + (idx >> 3);
            int cb = (idx & 7) * 16;
            uint4 v = *reinterpret_cast<uint4*>(smem + STG_OFF + swz128(row * 128 + cb));
            *reinterpret_cast<uint4*>(
                (char*)(Eb + (size_t)(qb * 128 + row) * SEQ + t * 64) + cb) = v;
        }
    };

    // full tile body (mask prefetch, QK, epi, PV, store)
    auto process = [&](int kb) {
        const uint32_t kbase = sb + 16384 + (kb & 3) * 16384;
        const uint32_t vbase = kbase + 8192;

        uint32_t m0r[8], m1r[8];
#pragma unroll
        for (int ni = 0; ni < 8; ni++) {
            int kcol = kb * 64 + ni * 8 + (lane & 3) * 2;
            m0r[ni] = *reinterpret_cast<const uint32_t*>(Mb + (size_t)q_r0 * SEQ + kcol);
            m1r[ni] = *reinterpret_cast<const uint32_t*>(Mb + (size_t)q_r1 * SEQ + kcol);
        }

        float acc[8][4];
#pragma unroll
        for (int ni = 0; ni < 8; ni++)
#pragma unroll
            for (int j = 0; j < 4; j++) acc[ni][j] = 0.f;

#pragma unroll
        for (int ki = 0; ki < 4; ki++) {
            uint32_t ah[4];
            {
                int row = w * 16 + (lane & 15);
                int kbyte = ki * 32 + ((lane >> 4) << 4);
                ldmx4(ah, sb + swz128(row * 128 + kbyte));
            }
#pragma unroll
            for (int pi = 0; pi < 4; pi++) {
                int nrow = pi * 16 + ((lane >> 4) << 3) + (lane & 7);
                int kbyte = ki * 32 + ((lane >> 3) & 1) * 16;
                uint32_t bh4[4];
                ldmx4(bh4, kbase + swz128(nrow * 128 + kbyte));
                mma_hf(acc[2 * pi], ah, bh4);
                mma_hf(acc[2 * pi + 1], ah, bh4 + 2);
            }
        }

        uint32_t e16[4][4];
#pragma unroll
        for (int ni = 0; ni < 8; ni++) {
            int kc2 = ni * 8 + (lane & 3) * 2;
            __half2 s0 = __floats2half2_rn(acc[ni][0], acc[ni][1]);
            __half2 s1 = __floats2half2_rn(acc[ni][2], acc[ni][3]);
            s0 = __hadd2(s0, *reinterpret_cast<__half2*>(&m0r[ni]));
            s1 = __hadd2(s1, *reinterpret_cast<__half2*>(&m1r[ni]));
            uint32_t e0 = h2ex2(*reinterpret_cast<uint32_t*>(&s0));
            uint32_t e1 = h2ex2(*reinterpret_cast<uint32_t*>(&s1));
            *reinterpret_cast<uint32_t*>(smem + STG_OFF + swz128(r0l * 128 + kc2 * 2)) = e0;
            *reinterpret_cast<uint32_t*>(smem + STG_OFF + swz128((r0l + 8) * 128 + kc2 * 2)) = e1;
            int ki = ni >> 1, hi = (ni & 1) * 2;
            e16[ki][hi + 0] = e0;
            e16[ki][hi + 1] = e1;
        }

#pragma unroll
        for (int ki = 0; ki < 4; ki++) {
            mma_hf(rsA, e16[ki], b_ones);
#pragma unroll
            for (int pi = 0; pi < 4; pi++) {
                int vrow = ki * 16 + (lane & 15);
                int vbyte = pi * 32 + ((lane >> 4) << 4);
                uint32_t vh4[4];
                ldmx4t(vh4, vbase + swz128(vrow * 128 + vbyte));
                mma_hf(O[2 * pi], e16[ki], vh4);
                mma_hf(O[2 * pi + 1], e16[ki], vh4 + 2);
            }
        }

        store_E(kb);
    };

    for (int p = 0; p < NKB / 2; p++) {
        const int kb0 = 2 * p;
        CP_WAIT(0);
        __syncthreads();   // one barrier per 2 tiles
        if (p >= 1 && kb0 + 3 < NKB) {   // refill stages freed by tiles kb0-2, kb0-1
            load_kv(kb0 + 2);
            load_kv(kb0 + 3);
        }
        process(kb0);
        process(kb0 + 1);
    }

    float ri0 = 1.f / rsA[0], ri1 = 1.f / rsA[2];
    if ((lane & 3) == 0) {
        rinv[(size_t)bhz * SEQ + q_r0] = ri0;
        rinv[(size_t)bhz * SEQ + q_r1] = ri1;
    }

    // epilogue: O * rinv * gate -> att2 (split2 fp16 layout [hi|lo])
#pragma unroll
    for (int ni = 0; ni < 8; ni++) {
        int d = ni * 8 + (lane & 3) * 2;
        int col = hh * HD + d;
#pragma unroll
        for (int rr = 0; rr < 2; rr++) {
            int qr = rr ? q_r1 : q_r0;
            float ri = rr ? ri1 : ri0;
            size_t gi = ((size_t)bb * SEQ + qr) * DIM + col;
            float2 g = *reinterpret_cast<const float2*>(gate + gi);
            float ox = O[ni][rr * 2 + 0] * ri * g.x;
            float oy = O[ni][rr * 2 + 1] * ri * g.y;
            __half hx = __float2half_rn(ox), hy = __float2half_rn(oy);
            __half2 hi2(hx, hy);
            __half2 lo2(__float2half_rn(ox - __half2float(hx)),
                        __float2half_rn(oy - __half2float(hy)));
            __half* rowp = att2 + ((size_t)bb * SEQ + qr) * K2;
            *reinterpret_cast<__half2*>(rowp + col) = hi2;
            *reinterpret_cast<__half2*>(rowp + DIM + col) = lo2;
        }
    }
}

// ======================= avg over heads (fp16 E) ===========================
__global__ __launch_bounds__(512) void avg_kernel(
    const __half* __restrict__ E, const float* __restrict__ rinv,
    float* __restrict__ avg)
{
    int bq = blockIdx.x;
    int b = bq >> 11, q = bq & 2047;
    int k4 = threadIdx.x * 4;
    float4 s = {0.f, 0.f, 0.f, 0.f};
#pragma unroll
    for (int h = 0; h < NH; h++) {
        float ri = rinv[(size_t)(b * NH + h) * SEQ + q] * (1.f / NH);
        const __half2* p = reinterpret_cast<const __half2*>(
            E + ((size_t)(b * NH + h) * SEQ + q) * SEQ + k4);
        float2 f0 = __half22float2(p[0]);
        float2 f1 = __half22float2(p[1]);
        s.x += f0.x * ri; s.y += f0.y * ri;
        s.z += f1.x * ri; s.w += f1.y * ri;
    }
    *reinterpret_cast<float4*>(avg + (size_t)bq * SEQ + k4) = s;
}

// ---------------- launch -----------------------------------------------------
extern "C" void kernel_launch(void* const* d_in, const int* in_sizes, int n_in,
                              void* d_out, int out_size)
{
    (void)in_sizes; (void)n_in; (void)out_size;
    const float* x    = (const float*)d_in[0];
    const float* mask = (const float*)d_in[1];
    const unsigned char* pad = (const unsigned char*)d_in[2];
    const float* Wq = (const float*)d_in[3];
    const float* bq = (const float*)d_in[4];
    const float* Wk = (const float*)d_in[5];
    const float* bk = (const float*)d_in[6];
    const float* Wv = (const float*)d_in[7];
    const float* bv = (const float*)d_in[8];
    const float* Wg = (const float*)d_in[9];
    const float* bg = (const float*)d_in[10];
    const float* Wo = (const float*)d_in[11];
    const float* bo = (const float*)d_in[12];
    float* out = (float*)d_out;

    float *gate, *rinv;
    __half *E, *qkh, *maskh, *a2, *w2;
    cudaGetSymbolAddress((void**)&gate, g_gate);
    cudaGetSymbolAddress((void**)&E, g_E);
    cudaGetSymbolAddress((void**)&rinv, g_rinv);
    cudaGetSymbolAddress((void**)&a2, g_a2);
    cudaGetSymbolAddress((void**)&w2, g_w2);
    cudaGetSymbolAddress((void**)&qkh, g_qkh);
    cudaGetSymbolAddress((void**)&maskh, g_maskh);

    static bool init0 = false;
    static cudaStream_t s2;
    static cudaEvent_t ev0, evT, ev1, ev2, ev3;
    if (!init0) {
        cudaFuncSetAttribute(gemm_hmma, cudaFuncAttributeMaxDynamicSharedMemorySize, GEMM_SMEM);
        cudaFuncSetAttribute(flash_attn, cudaFuncAttributeMaxDynamicSharedMemorySize, FL_SMEM);
        cudaStreamCreateWithFlags(&s2, cudaStreamNonBlocking);
        cudaEventCreateWithFlags(&ev0, cudaEventDisableTiming);
        cudaEventCreateWithFlags(&evT, cudaEventDisableTiming);
        cudaEventCreateWithFlags(&ev1, cudaEventDisableTiming);
        cudaEventCreateWithFlags(&ev2, cudaEventDisableTiming);
        cudaEventCreateWithFlags(&ev3, cudaEventDisableTiming);
        init0 = true;
    }

    // fork: weight transpose + mask/pad fold on s2 || x split on main
    cudaEventRecord(ev0, 0);
    cudaStreamWaitEvent(s2, ev0, 0);
    transpose_split2_all<<<dim3(DIM / 32, DIM / 32, 5), dim3(32, 32), 0, s2>>>(
        Wq, Wk, Wv, Wg, Wo, w2);
    cudaEventRecord(evT, s2);
    mask_pad_to_half<<<dim3((SEQ * SEQ) / 1024, BB), 256, 0, s2>>>(mask, pad, maskh);
    cudaEventRecord(ev1, s2);

    split2_f32<<<(MTOT * DIM) / 1024, 256>>>(x, a2);

    cudaStreamWaitEvent(0, evT, 0);
    gemm_hmma<<<dim3(DIM / 128, MTOT / 128, 4), 256, GEMM_SMEM>>>(
        a2, w2, bq, bk, bv, bg, gate, qkh, nullptr, 0);

    cudaStreamWaitEvent(0, ev1, 0);
    flash_attn<<<dim3(1, SEQ / 128, NBH), 256, FL_SMEM>>>(
        qkh, maskh, gate, E, rinv, a2);

    cudaEventRecord(ev2, 0);
    cudaStreamWaitEvent(s2, ev2, 0);
    avg_kernel<<<BB * SEQ, 512, 0, s2>>>(E, rinv, out + (size_t)MTOT * DIM);
    cudaEventRecord(ev3, s2);

    gemm_hmma<<<dim3(DIM / 128, MTOT / 128, 1), 256, GEMM_SMEM>>>(
        a2, w2 + 4ull * DIM * K2, bo, bo, bo, bo, nullptr, nullptr, out, 1);

    cudaStreamWaitEvent(0, ev3, 0);
}

// round 17
// speedup vs baseline: 1.0187x; 1.0187x over previous
#include <cuda_runtime.h>
#include <cuda_bf16.h>
#include <cuda_fp16.h>
#include <math.h>
#include <stdint.h>

// Fixed problem shape
#define BB 2
#define SEQ 2048
#define DIM 1024
#define NH 16
#define HD 64
#define MTOT (BB * SEQ)            // 4096
#define K2 (2 * DIM)               // 2048 (2-term fp16 split layout)
#define NSTG2 32                   // K2 / 64
#define NBH (BB * NH)              // 32
#define LOG2E 1.44269504f

// ---------------- scratch ----------------------------------------------------
__device__ float g_gate[(size_t)MTOT * DIM];           // sigmoid gate fp32
__device__ __half g_E[(size_t)NBH * SEQ * SEQ];        // unnormalized exp, fp16
__device__ float g_rinv[(size_t)NBH * SEQ];            // 1/rowsum
__device__ __half g_a2[(size_t)MTOT * K2];             // [Ah|Al] fp16 (x, then att)
__device__ __half g_w2[5ull * DIM * K2];               // [Wh|Wh] fp16 N-major
__device__ __half g_qkh[3ull * 2 * NBH * SEQ * HD];    // q,k,v per-head fp16 (hi slots)
__device__ __half g_maskh[(size_t)BB * SEQ * SEQ];     // (mask*log2e) | pad->-60000

// ======================= helpers ===========================================
__device__ __forceinline__ uint32_t smem_u32(const void* p) {
    uint32_t a;
    asm("{ .reg .u64 t; cvta.to.shared.u64 t, %1; cvt.u32.u64 %0, t; }"
        : "=r"(a) : "l"(p));
    return a;
}
__device__ __forceinline__ uint32_t swz128(uint32_t o) { return o ^ ((o >> 3) & 0x70); }

__device__ __forceinline__ void cp_async16(uint32_t dst, const void* src) {
    asm volatile("cp.async.cg.shared.global [%0], [%1], 16;" :: "r"(dst), "l"(src));
}
#define CP_COMMIT() asm volatile("cp.async.commit_group;" ::: "memory")
#define CP_WAIT(n)  asm volatile("cp.async.wait_group %0;" :: "n"(n) : "memory")

__device__ __forceinline__ void ldmx4(uint32_t* r, uint32_t addr) {
    asm volatile("ldmatrix.sync.aligned.m8n8.x4.shared.b16 {%0,%1,%2,%3}, [%4];"
                 : "=r"(r[0]), "=r"(r[1]), "=r"(r[2]), "=r"(r[3]) : "r"(addr));
}
__device__ __forceinline__ void ldmx4t(uint32_t* r, uint32_t addr) {
    asm volatile("ldmatrix.sync.aligned.m8n8.x4.trans.shared.b16 {%0,%1,%2,%3}, [%4];"
                 : "=r"(r[0]), "=r"(r[1]), "=r"(r[2]), "=r"(r[3]) : "r"(addr));
}
__device__ __forceinline__ void mma_hf(float* c, const uint32_t* a, const uint32_t* b) {
    asm volatile(
        "mma.sync.aligned.m16n8k16.row.col.f32.f16.f16.f32 "
        "{%0,%1,%2,%3}, {%4,%5,%6,%7}, {%8,%9}, {%0,%1,%2,%3};"
        : "+f"(c[0]), "+f"(c[1]), "+f"(c[2]), "+f"(c[3])
        : "r"(a[0]), "r"(a[1]), "r"(a[2]), "r"(a[3]), "r"(b[0]), "r"(b[1]));
}
__device__ __forceinline__ uint32_t h2ex2(uint32_t s) {
    uint32_t r;
    asm("ex2.approx.f16x2 %0, %1;" : "=r"(r) : "r"(s));
    return r;
}

// ======================= conversions =======================================
__global__ __launch_bounds__(256) void split2_f32(const float* __restrict__ x,
                                                  __half* __restrict__ A2) {
    size_t i = ((size_t)blockIdx.x * 256 + threadIdx.x) * 4;
    size_t m = i / DIM, k = i % DIM;
    float4 v = *reinterpret_cast<const float4*>(x + i);
    __half h0 = __float2half_rn(v.x), h1 = __float2half_rn(v.y);
    __half h2 = __float2half_rn(v.z), h3 = __float2half_rn(v.w);
    __half2 hA(h0, h1), hB(h2, h3);
    __half2 lA(__float2half_rn(v.x - __half2float(h0)),
               __float2half_rn(v.y - __half2float(h1)));
    __half2 lB(__float2half_rn(v.z - __half2float(h2)),
               __float2half_rn(v.w - __half2float(h3)));
    __half* row = A2 + m * K2;
    *reinterpret_cast<__half2*>(row + k) = hA;
    *reinterpret_cast<__half2*>(row + k + 2) = hB;
    *reinterpret_cast<__half2*>(row + DIM + k) = lA;
    *reinterpret_cast<__half2*>(row + DIM + k + 2) = lB;
}

__global__ __launch_bounds__(1024) void transpose_split2_all(
    const float* __restrict__ W0, const float* __restrict__ W1,
    const float* __restrict__ W2p, const float* __restrict__ W3p,
    const float* __restrict__ W4, __half* __restrict__ out)
{
    __shared__ float t[32][33];
    int z = blockIdx.z;
    const float* W = (z == 0) ? W0 : (z == 1) ? W1 : (z == 2) ? W2p : (z == 3) ? W3p : W4;
    int tx = threadIdx.x, ty = threadIdx.y;
    int k0 = blockIdx.y * 32, n0 = blockIdx.x * 32;
    t[ty][tx] = W[(size_t)(k0 + ty) * DIM + n0 + tx];
    __syncthreads();
    float v = t[tx][ty];
    __half h = __float2half_rn(v);
    __half* row = out + (size_t)z * DIM * K2 + (size_t)(n0 + ty) * K2;
    row[k0 + tx] = h;
    row[DIM + k0 + tx] = h;
}

// mask -> fp16 * log2e, padded keys -> -60000 (ex2 underflows to 0)
__global__ __launch_bounds__(256) void mask_pad_to_half(
    const float* __restrict__ m, const unsigned char* __restrict__ pad,
    __half* __restrict__ mh)
{
    int b = blockIdx.y;
    size_t i = ((size_t)blockIdx.x * 256 + threadIdx.x) * 4;
    int kc = (int)(i & (SEQ - 1));
    float4 v = *reinterpret_cast<const float4*>(m + i);
    uchar4 pd = *reinterpret_cast<const uchar4*>(pad + b * SEQ + kc);
    const float NEG = -60000.f;
    float a0 = pd.x ? NEG : v.x * LOG2E;
    float a1 = pd.y ? NEG : v.y * LOG2E;
    float a2v = pd.z ? NEG : v.z * LOG2E;
    float a3 = pd.w ? NEG : v.w * LOG2E;
    __half2 A = __floats2half2_rn(a0, a1);
    __half2 Bv = __floats2half2_rn(a2v, a3);
    __half* dst = mh + (size_t)b * SEQ * SEQ + i;
    *reinterpret_cast<__half2*>(dst) = A;
    *reinterpret_cast<__half2*>(dst + 2) = Bv;
}

// ======================= HMMA fp16 dense GEMM (3-stage) ====================
#define GEMM_SMEM (96 * 1024)
__global__ __launch_bounds__(256, 2) void gemm_hmma(
    const __half* __restrict__ A2, const __half* __restrict__ W2base,
    const float* b0, const float* b1, const float* b2, const float* b3,
    float* __restrict__ gateOut, __half* __restrict__ qkhOut,
    float* __restrict__ fOut, int mode)
{
    extern __shared__ char smem[];
    const uint32_t sb = smem_u32(smem);
    const int tid = threadIdx.x;
    const int wid = tid >> 5, lane = tid & 31;
    const int wm = wid & 3, wn = wid >> 2;
    const int z = blockIdx.z;
    const int m0 = blockIdx.y * 128, n0 = blockIdx.x * 128;

    const int nstg = (mode == 1) ? NSTG2 : (NSTG2 / 2);

    const __half* W2 = W2base + (size_t)z * DIM * K2;
    const float* bias = (z == 0) ? b0 : (z == 1) ? b1 : (z == 2) ? b2 : b3;

    const char* gA = (const char*)(A2 + (size_t)m0 * K2);
    const char* gB = (const char*)(W2 + (size_t)n0 * K2);

    auto load_stage = [&](int s) {
        const uint32_t base = sb + (s % 3) * 32768;
        const int kb = s * 128;
#pragma unroll
        for (int i = 0; i < 4; i++) {
            int c = tid + 256 * i;
            int row = c >> 3, cb = (c & 7) * 16;
            uint32_t d = swz128(row * 128 + cb);
            size_t src = (size_t)row * (K2 * 2) + kb + cb;
            cp_async16(base + d, gA + src);
            cp_async16(base + 16384 + d, gB + src);
        }
        CP_COMMIT();
    };

    float acc[2][8][4];
#pragma unroll
    for (int mi = 0; mi < 2; mi++)
#pragma unroll
        for (int ni = 0; ni < 8; ni++)
#pragma unroll
            for (int j = 0; j < 4; j++) acc[mi][ni][j] = 0.f;

    load_stage(0);
    load_stage(1);
    load_stage(2);

    for (int s = 0; s < nstg; s++) {
        if (s >= nstg - 1)      { CP_WAIT(0); }
        else if (s == nstg - 2) { CP_WAIT(1); }
        else                    { CP_WAIT(2); }
        __syncthreads();
        const uint32_t abase = sb + (s % 3) * 32768;
        const uint32_t bbase = abase + 16384;
#pragma unroll
        for (int ki = 0; ki < 4; ki++) {
            uint32_t a[2][4];
#pragma unroll
            for (int mi = 0; mi < 2; mi++) {
                int row = wm * 32 + mi * 16 + (lane & 15);
                int kb = ki * 32 + ((lane >> 4) << 4);
                ldmx4(a[mi], abase + swz128(row * 128 + kb));
            }
#pragma unroll
            for (int pi = 0; pi < 4; pi++) {
                int nrow = wn * 64 + pi * 16 + ((lane >> 4) << 3) + (lane & 7);
                int kb = ki * 32 + ((lane >> 3) & 1) * 16;
                uint32_t b[4];
                ldmx4(b, bbase + swz128(nrow * 128 + kb));
#pragma unroll
                for (int mi = 0; mi < 2; mi++) {
                    mma_hf(acc[mi][2 * pi], a[mi], b);
                    mma_hf(acc[mi][2 * pi + 1], a[mi], b + 2);
                }
            }
        }
        __syncthreads();
        if (s + 3 < nstg) load_stage(s + 3);
    }

    const int rbase = m0 + wm * 32;
    const int cbase = n0 + wn * 64;
#pragma unroll
    for (int mi = 0; mi < 2; mi++) {
#pragma unroll
        for (int ni = 0; ni < 8; ni++) {
            int row = rbase + mi * 16 + (lane >> 2);
            int col = cbase + ni * 8 + (lane & 3) * 2;
            float bx = bias[col], by = bias[col + 1];
            float vx0 = acc[mi][ni][0] + bx, vy0 = acc[mi][ni][1] + by;
            float vx1 = acc[mi][ni][2] + bx, vy1 = acc[mi][ni][3] + by;
            if (mode == 1) {
                *reinterpret_cast<float2*>(&fOut[(size_t)row * DIM + col]) =
                    make_float2(vx0, vy0);
                *reinterpret_cast<float2*>(&fOut[(size_t)(row + 8) * DIM + col]) =
                    make_float2(vx1, vy1);
            } else if (z == 3) {
                float2 g0 = {1.f / (1.f + expf(-vx0)), 1.f / (1.f + expf(-vy0))};
                float2 g1 = {1.f / (1.f + expf(-vx1)), 1.f / (1.f + expf(-vy1))};
                *reinterpret_cast<float2*>(&gateOut[(size_t)row * DIM + col]) = g0;
                *reinterpret_cast<float2*>(&gateOut[(size_t)(row + 8) * DIM + col]) = g1;
            } else {
                if (z == 0) {
                    const float sc = 0.125f * LOG2E;
                    vx0 *= sc; vy0 *= sc; vx1 *= sc; vy1 *= sc;
                }
                int h = col >> 6, d = col & 63;
#pragma unroll
                for (int rr = 0; rr < 2; rr++) {
                    int rw = row + rr * 8;
                    float vx = rr ? vx1 : vx0, vy = rr ? vy1 : vy0;
                    int bh = (rw >> 11) * NH + h, s = rw & 2047;
                    __half2 hi2(__float2half_rn(vx), __float2half_rn(vy));
                    size_t bi = ((((size_t)z * 2 + 0) * NBH + bh) * SEQ + s) * HD + d;
                    *reinterpret_cast<__half2*>(qkhOut + bi) = hi2;
                }
            }
        }
    }
}

// ======================= fused flash attention v11 =========================
// Q fragments resident in registers (loaded once via staging area).
// QK 1-term fp16 log2 domain, E = ex2.approx.f16x2(S + foldedMask), PV 1-term.
// Rowsum via E @ ones. One barrier per k-tile (skipped at kb=0).
// smem: stages 0..3x16K (48K) | staging 48K (16K, Q landing then E staging).
// Total 64K, 2 CTAs/SM.
#define FL_SMEM (64 * 1024)
#define STG_OFF (48 * 1024)
#define NKB 32
__global__ __launch_bounds__(256, 2) void flash_attn(
    const __half* __restrict__ qkh, const __half* __restrict__ maskh,
    const float* __restrict__ gate,
    __half* __restrict__ E, float* __restrict__ rinv,
    __half* __restrict__ att2)
{
    extern __shared__ char smem[];
    const uint32_t sb = smem_u32(smem);
    const int tid = threadIdx.x;
    const int w = tid >> 5, lane = tid & 31;
    const int bhz = blockIdx.z, qb = blockIdx.y;
    const int bb = bhz >> 4, hh = bhz & 15;

    const __half* Qh = qkh + ((size_t)(0 * 2 + 0) * NBH + bhz) * SEQ * HD;
    const __half* Kh = qkh + ((size_t)(1 * 2 + 0) * NBH + bhz) * SEQ * HD;
    const __half* Vh = qkh + ((size_t)(2 * 2 + 0) * NBH + bhz) * SEQ * HD;
    const __half* Mb = maskh + (size_t)bb * SEQ * SEQ;

    // land Q in the staging area (bundled into cp.async group 0)
#pragma unroll
    for (int i = 0; i < 4; i++) {
        int c = tid + 256 * i;
        int row = c >> 3, cb = (c & 7) * 16;
        uint32_t d = swz128(row * 128 + cb);
        size_t src = (size_t)(qb * 128 + row) * (HD * 2) + cb;
        cp_async16(sb + STG_OFF + d, (const char*)Qh + src);
    }
    auto load_kv = [&](int kb) {
        const uint32_t base = sb + (kb % 3) * 16384;
#pragma unroll
        for (int i = 0; i < 2; i++) {
            int c = tid + 256 * i;
            int row = c >> 3, cb = (c & 7) * 16;
            uint32_t d = swz128(row * 128 + cb);
            size_t src = (size_t)(kb * 64 + row) * (HD * 2) + cb;
            cp_async16(base + d, (const char*)Kh + src);
            cp_async16(base + 8192 + d, (const char*)Vh + src);
        }
        CP_COMMIT();
    };
    load_kv(0);     // group 0: Q + kv0
    load_kv(1);
    load_kv(2);

    // Q fragments -> registers (warp-local staging rows)
    CP_WAIT(2);          // group 0 complete
    __syncthreads();     // cross-thread visibility of Q
    uint32_t qf[4][4];
#pragma unroll
    for (int ki = 0; ki < 4; ki++) {
        int row = w * 16 + (lane & 15);
        int kbyte = ki * 32 + ((lane >> 4) << 4);
        ldmx4(qf[ki], sb + STG_OFF + swz128(row * 128 + kbyte));
    }
    // staging rows are warp-local for both Q reads and E stores: no barrier

    float O[8][4];
#pragma unroll
    for (int ni = 0; ni < 8; ni++)
#pragma unroll
        for (int j = 0; j < 4; j++) O[ni][j] = 0.f;

    float rsA[4] = {0.f, 0.f, 0.f, 0.f};
    const uint32_t ONE2 = 0x3C003C00u;
    const uint32_t b_ones[2] = {ONE2, ONE2};

    const int r0l = w * 16 + (lane >> 2);
    const int q_r0 = qb * 128 + r0l;
    const int q_r1 = q_r0 + 8;
    __half* Eb = E + (size_t)bhz * SEQ * SEQ;

    // warp-local coalesced E store (each warp owns staging rows [16w,16w+16))
    auto store_E = [&](int t) {
#pragma unroll
        for (int i = 0; i < 4; i++) {
            int idx = i * 32 + lane;
            int row = w * 16 + (idx >> 3);
            int cb = (idx & 7) * 16;
            uint4 v = *reinterpret_cast<uint4*>(smem + STG_OFF + swz128(row * 128 + cb));
            *reinterpret_cast<uint4*>(
                (char*)(Eb + (size_t)(qb * 128 + row) * SEQ + t * 64) + cb) = v;
        }
    };

    for (int kb = 0; kb < NKB; kb++) {
        if (kb > 0) {
            if (kb == NKB - 1) { CP_WAIT(0); } else { CP_WAIT(1); }
            __syncthreads();   // stage kb visible + tile kb-1 reads done
            if (kb + 2 < NKB) load_kv(kb + 2);
        }
        const uint32_t kbase = sb + (kb % 3) * 16384;
        const uint32_t vbase = kbase + 8192;

        // prefetch folded mask (fp16) — independent of MMAs
        uint32_t m0r[8], m1r[8];
#pragma unroll
        for (int ni = 0; ni < 8; ni++) {
            int kcol = kb * 64 + ni * 8 + (lane & 3) * 2;
            m0r[ni] = *reinterpret_cast<const uint32_t*>(Mb + (size_t)q_r0 * SEQ + kcol);
            m1r[ni] = *reinterpret_cast<const uint32_t*>(Mb + (size_t)q_r1 * SEQ + kcol);
        }

        // ---- S = Q K^T (1-term fp16, log2 domain; Q from registers) ----
        float acc[8][4];
#pragma unroll
        for (int ni = 0; ni < 8; ni++)
#pragma unroll
            for (int j = 0; j < 4; j++) acc[ni][j] = 0.f;

#pragma unroll
        for (int ki = 0; ki < 4; ki++) {
#pragma unroll
            for (int pi = 0; pi < 4; pi++) {
                int nrow = pi * 16 + ((lane >> 4) << 3) + (lane & 7);
                int kbyte = ki * 32 + ((lane >> 3) & 1) * 16;
                uint32_t bh4[4];
                ldmx4(bh4, kbase + swz128(nrow * 128 + kbyte));
                mma_hf(acc[2 * pi], qf[ki], bh4);
                mma_hf(acc[2 * pi + 1], qf[ki], bh4 + 2);
            }
        }

        // ---- epilogue: E = ex2(S + mask), stage (own rows only), pack ----
        uint32_t e16[4][4];
#pragma unroll
        for (int ni = 0; ni < 8; ni++) {
            int kc2 = ni * 8 + (lane & 3) * 2;
            __half2 s0 = __floats2half2_rn(acc[ni][0], acc[ni][1]);
            __half2 s1 = __floats2half2_rn(acc[ni][2], acc[ni][3]);
            s0 = __hadd2(s0, *reinterpret_cast<__half2*>(&m0r[ni]));
            s1 = __hadd2(s1, *reinterpret_cast<__half2*>(&m1r[ni]));
            uint32_t e0 = h2ex2(*reinterpret_cast<uint32_t*>(&s0));
            uint32_t e1 = h2ex2(*reinterpret_cast<uint32_t*>(&s1));
            *reinterpret_cast<uint32_t*>(smem + STG_OFF + swz128(r0l * 128 + kc2 * 2)) = e0;
            *reinterpret_cast<uint32_t*>(smem + STG_OFF + swz128((r0l + 8) * 128 + kc2 * 2)) = e1;
            int ki = ni >> 1, hi = (ni & 1) * 2;
            e16[ki][hi + 0] = e0;
            e16[ki][hi + 1] = e1;
        }

        // ---- O += E @ V ; rowsum += E @ ones (tensor pipe) ----
#pragma unroll
        for (int ki = 0; ki < 4; ki++) {
            mma_hf(rsA, e16[ki], b_ones);
#pragma unroll
            for (int pi = 0; pi < 4; pi++) {
                int vrow = ki * 16 + (lane & 15);
                int vbyte = pi * 32 + ((lane >> 4) << 4);
                uint32_t vh4[4];
                ldmx4t(vh4, vbase + swz128(vrow * 128 + vbyte));
                mma_hf(O[2 * pi], e16[ki], vh4);
                mma_hf(O[2 * pi + 1], e16[ki], vh4 + 2);
            }
        }

        store_E(kb);   // warp-local, no barrier needed
    }

    float ri0 = 1.f / rsA[0], ri1 = 1.f / rsA[2];
    if ((lane & 3) == 0) {
        rinv[(size_t)bhz * SEQ + q_r0] = ri0;
        rinv[(size_t)bhz * SEQ + q_r1] = ri1;
    }

    // epilogue: O * rinv * gate -> att2 (split2 fp16 layout [hi|lo])
#pragma unroll
    for (int ni = 0; ni < 8; ni++) {
        int d = ni * 8 + (lane & 3) * 2;
        int col = hh * HD + d;
#pragma unroll
        for (int rr = 0; rr < 2; rr++) {
            int qr = rr ? q_r1 : q_r0;
            float ri = rr ? ri1 : ri0;
            size_t gi = ((size_t)bb * SEQ + qr) * DIM + col;
            float2 g = *reinterpret_cast<const float2*>(gate + gi);
            float ox = O[ni][rr * 2 + 0] * ri * g.x;
            float oy = O[ni][rr * 2 + 1] * ri * g.y;
            __half hx = __float2half_rn(ox), hy = __float2half_rn(oy);
            __half2 hi2(hx, hy);
            __half2 lo2(__float2half_rn(ox - __half2float(hx)),
                        __float2half_rn(oy - __half2float(hy)));
            __half* rowp = att2 + ((size_t)bb * SEQ + qr) * K2;
            *reinterpret_cast<__half2*>(rowp + col) = hi2;
            *reinterpret_cast<__half2*>(rowp + DIM + col) = lo2;
        }
    }
}

// ======================= avg over heads (fp16 E) ===========================
__global__ __launch_bounds__(512) void avg_kernel(
    const __half* __restrict__ E, const float* __restrict__ rinv,
    float* __restrict__ avg)
{
    int bq = blockIdx.x;
    int b = bq >> 11, q = bq & 2047;
    int k4 = threadIdx.x * 4;
    float4 s = {0.f, 0.f, 0.f, 0.f};
#pragma unroll
    for (int h = 0; h < NH; h++) {
        float ri = rinv[(size_t)(b * NH + h) * SEQ + q] * (1.f / NH);
        const __half2* p = reinterpret_cast<const __half2*>(
            E + ((size_t)(b * NH + h) * SEQ + q) * SEQ + k4);
        float2 f0 = __half22float2(p[0]);
        float2 f1 = __half22float2(p[1]);
        s.x += f0.x * ri; s.y += f0.y * ri;
        s.z += f1.x * ri; s.w += f1.y * ri;
    }
    *reinterpret_cast<float4*>(avg + (size_t)bq * SEQ + k4) = s;
}

// ---------------- launch -----------------------------------------------------
extern "C" void kernel_launch(void* const* d_in, const int* in_sizes, int n_in,
                              void* d_out, int out_size)
{
    (void)in_sizes; (void)n_in; (void)out_size;
    const float* x    = (const float*)d_in[0];
    const float* mask = (const float*)d_in[1];
    const unsigned char* pad = (const unsigned char*)d_in[2];
    const float* Wq = (const float*)d_in[3];
    const float* bq = (const float*)d_in[4];
    const float* Wk = (const float*)d_in[5];
    const float* bk = (const float*)d_in[6];
    const float* Wv = (const float*)d_in[7];
    const float* bv = (const float*)d_in[8];
    const float* Wg = (const float*)d_in[9];
    const float* bg = (const float*)d_in[10];
    const float* Wo = (const float*)d_in[11];
    const float* bo = (const float*)d_in[12];
    float* out = (float*)d_out;

    float *gate, *rinv;
    __half *E, *qkh, *maskh, *a2, *w2;
    cudaGetSymbolAddress((void**)&gate, g_gate);
    cudaGetSymbolAddress((void**)&E, g_E);
    cudaGetSymbolAddress((void**)&rinv, g_rinv);
    cudaGetSymbolAddress((void**)&a2, g_a2);
    cudaGetSymbolAddress((void**)&w2, g_w2);
    cudaGetSymbolAddress((void**)&qkh, g_qkh);
    cudaGetSymbolAddress((void**)&maskh, g_maskh);

    static bool init0 = false;
    static cudaStream_t s2;
    static cudaEvent_t ev0, evT, ev1, ev2, ev3;
    if (!init0) {
        cudaFuncSetAttribute(gemm_hmma, cudaFuncAttributeMaxDynamicSharedMemorySize, GEMM_SMEM);
        cudaFuncSetAttribute(flash_attn, cudaFuncAttributeMaxDynamicSharedMemorySize, FL_SMEM);
        cudaStreamCreateWithFlags(&s2, cudaStreamNonBlocking);
        cudaEventCreateWithFlags(&ev0, cudaEventDisableTiming);
        cudaEventCreateWithFlags(&evT, cudaEventDisableTiming);
        cudaEventCreateWithFlags(&ev1, cudaEventDisableTiming);
        cudaEventCreateWithFlags(&ev2, cudaEventDisableTiming);
        cudaEventCreateWithFlags(&ev3, cudaEventDisableTiming);
        init0 = true;
    }

    // fork: weight transpose + mask/pad fold on s2 || x split on main
    cudaEventRecord(ev0, 0);
    cudaStreamWaitEvent(s2, ev0, 0);
    transpose_split2_all<<<dim3(DIM / 32, DIM / 32, 5), dim3(32, 32), 0, s2>>>(
        Wq, Wk, Wv, Wg, Wo, w2);
    cudaEventRecord(evT, s2);
    mask_pad_to_half<<<dim3((SEQ * SEQ) / 1024, BB), 256, 0, s2>>>(mask, pad, maskh);
    cudaEventRecord(ev1, s2);

    split2_f32<<<(MTOT * DIM) / 1024, 256>>>(x, a2);

    cudaStreamWaitEvent(0, evT, 0);
    gemm_hmma<<<dim3(DIM / 128, MTOT / 128, 4), 256, GEMM_SMEM>>>(
        a2, w2, bq, bk, bv, bg, gate, qkh, nullptr, 0);

    cudaStreamWaitEvent(0, ev1, 0);
    flash_attn<<<dim3(1, SEQ / 128, NBH), 256, FL_SMEM>>>(
        qkh, maskh, gate, E, rinv, a2);

    cudaEventRecord(ev2, 0);
    cudaStreamWaitEvent(s2, ev2, 0);
    avg_kernel<<<BB * SEQ, 512, 0, s2>>>(E, rinv, out + (size_t)MTOT * DIM);
    cudaEventRecord(ev3, s2);

    gemm_hmma<<<dim3(DIM / 128, MTOT / 128, 1), 256, GEMM_SMEM>>>(
        a2, w2 + 4ull * DIM * K2, bo, bo, bo, bo, nullptr, nullptr, out, 1);

    cudaStreamWaitEvent(0, ev3, 0);
}